// round 6
// baseline (speedup 1.0000x reference)
#include <cuda_runtime.h>
#include <cuda_bf16.h>
#include <cstdint>

// Problem shape (fixed by the dataset)
#define BATCH 2
#define SEQ   2048
#define DIM   1024
#define NHEAD 16
#define DHEAD 64
#define MROWS (BATCH * SEQ)          // 4096
#define NQKV  (3 * DIM)              // 3072
#define KTOT  1024

// ---------------------------------------------------------------------------
// Scratch (allocation-free rule: __device__ globals), all bf16 split-2 pairs
// ---------------------------------------------------------------------------
__device__ __nv_bfloat16 s_a_hi[MROWS * KTOT];   // GEMM A: x, then attention out
__device__ __nv_bfloat16 s_a_lo[MROWS * KTOT];
__device__ __nv_bfloat16 s_wq_hi[NQKV * KTOT];   // w_attn^T [3072,1024]
__device__ __nv_bfloat16 s_wq_lo[NQKV * KTOT];
__device__ __nv_bfloat16 s_wp_hi[DIM * KTOT];    // w_proj^T [1024,1024]
__device__ __nv_bfloat16 s_wp_lo[DIM * KTOT];
// attention operands, written by QKV epilogue
__device__ __nv_bfloat16 s_q_hi[BATCH * NHEAD * SEQ * DHEAD];  // [bh,s,dh], q*0.125
__device__ __nv_bfloat16 s_q_lo[BATCH * NHEAD * SEQ * DHEAD];
__device__ __nv_bfloat16 s_k_hi[BATCH * NHEAD * SEQ * DHEAD];  // [bh,s,dh]
__device__ __nv_bfloat16 s_k_lo[BATCH * NHEAD * SEQ * DHEAD];
__device__ __nv_bfloat16 s_vt_hi[BATCH * NHEAD * DHEAD * SEQ]; // [bh,dh,s]
__device__ __nv_bfloat16 s_vt_lo[BATCH * NHEAD * DHEAD * SEQ];

// ---------------------------------------------------------------------------
// PTX helpers (baseline ISA — compiles for sm_103)
// ---------------------------------------------------------------------------
__device__ __forceinline__ uint32_t smem_u32(const void* p) {
    uint32_t a;
    asm("{ .reg .u64 t; cvta.to.shared.u64 t, %1; cvt.u32.u64 %0, t; }"
        : "=r"(a) : "l"(p));
    return a;
}
__device__ __forceinline__ void ldsm4(uint32_t addr, uint32_t& r0, uint32_t& r1,
                                      uint32_t& r2, uint32_t& r3) {
    asm volatile("ldmatrix.sync.aligned.m8n8.x4.shared.b16 {%0,%1,%2,%3}, [%4];"
                 : "=r"(r0), "=r"(r1), "=r"(r2), "=r"(r3) : "r"(addr));
}
__device__ __forceinline__ void mma_bf16(float& c0, float& c1, float& c2, float& c3,
                                         uint32_t a0, uint32_t a1, uint32_t a2, uint32_t a3,
                                         uint32_t b0, uint32_t b1) {
    asm volatile("mma.sync.aligned.m16n8k16.row.col.f32.bf16.bf16.f32 "
                 "{%0,%1,%2,%3}, {%4,%5,%6,%7}, {%8,%9}, {%0,%1,%2,%3};"
                 : "+f"(c0), "+f"(c1), "+f"(c2), "+f"(c3)
                 : "r"(a0), "r"(a1), "r"(a2), "r"(a3), "r"(b0), "r"(b1));
}
__device__ __forceinline__ void cp16(uint32_t saddr, const void* g) {
    asm volatile("cp.async.cg.shared.global [%0], [%1], 16;"
                 :: "r"(saddr), "l"(g) : "memory");
}
__device__ __forceinline__ void cp_commit() {
    asm volatile("cp.async.commit_group;" ::: "memory");
}
template <int N>
__device__ __forceinline__ void cp_wait() {
    asm volatile("cp.async.wait_group %0;" :: "n"(N) : "memory");
}
__device__ __forceinline__ void split2(float v, __nv_bfloat16& h, __nv_bfloat16& l) {
    h = __float2bfloat16_rn(v);
    l = __float2bfloat16_rn(v - __bfloat162float(h));
}
__device__ __forceinline__ uint32_t packbf(__nv_bfloat16 a, __nv_bfloat16 b) {
    return (uint32_t)__bfloat16_as_ushort(a) | ((uint32_t)__bfloat16_as_ushort(b) << 16);
}

// ---------------------------------------------------------------------------
// Prep kernels
// ---------------------------------------------------------------------------
__global__ __launch_bounds__(256) void split_kernel(
    const float* __restrict__ src, __nv_bfloat16* __restrict__ hi,
    __nv_bfloat16* __restrict__ lo, int n4)
{
    int i = blockIdx.x * 256 + threadIdx.x;
    if (i >= n4) return;
    float4 v = ((const float4*)src)[i];
    __nv_bfloat16 h0, l0, h1, l1, h2, l2, h3, l3;
    split2(v.x, h0, l0); split2(v.y, h1, l1);
    split2(v.z, h2, l2); split2(v.w, h3, l3);
    uint2 uh = make_uint2(packbf(h0, h1), packbf(h2, h3));
    uint2 ul = make_uint2(packbf(l0, l1), packbf(l2, l3));
    *(uint2*)(hi + (size_t)i * 4) = uh;
    *(uint2*)(lo + (size_t)i * 4) = ul;
}

__global__ __launch_bounds__(256) void transp_split_kernel(
    const float* __restrict__ w, int K, int N,
    __nv_bfloat16* __restrict__ out_hi, __nv_bfloat16* __restrict__ out_lo)
{
    __shared__ float t[32][33];
    const int tx = threadIdx.x, ty = threadIdx.y;
    const int n0 = blockIdx.x * 32, k0 = blockIdx.y * 32;
#pragma unroll
    for (int i = 0; i < 4; ++i)
        t[ty + i * 8][tx] = w[(size_t)(k0 + ty + i * 8) * N + n0 + tx];
    __syncthreads();
#pragma unroll
    for (int i = 0; i < 4; ++i) {
        const int n = n0 + ty + i * 8;
        float v = t[tx][ty + i * 8];
        __nv_bfloat16 h, l;
        split2(v, h, l);
        out_hi[(size_t)n * K + k0 + tx] = h;
        out_lo[(size_t)n * K + k0 + tx] = l;
    }
}

// ---------------------------------------------------------------------------
// HMMA GEMM with cp.async 2-stage pipeline.
// D[M,N] = A @ B^T + bias, bf16 split-2 (3 products, fp32 accum).
// mode 0: QKV epilogue -> bf16 split q/k (k-major) and vt (transposed)
// mode 1: plain fp32 out
// ---------------------------------------------------------------------------
#define BM 128
#define BN 128
#define BK 32
#define ROWB 80
#define NKT (KTOT / BK)          // 32
#define OFF_ALO 10240
#define OFF_BHI 20480
#define OFF_BLO 30720
#define STG_BYTES 40960
#define GSM_BYTES (2 * STG_BYTES)   // 81920

__global__ __launch_bounds__(256) void tc_gemm_kernel(
    const __nv_bfloat16* __restrict__ Ahi, const __nv_bfloat16* __restrict__ Alo,
    const __nv_bfloat16* __restrict__ Bhi, const __nv_bfloat16* __restrict__ Blo,
    const float* __restrict__ bias, float* __restrict__ outp, int mode)
{
    extern __shared__ char gsm[];
    const uint32_t sb = smem_u32(gsm);

    const int tid  = threadIdx.x;
    const int w    = tid >> 5;
    const int lane = tid & 31;
    const int m0 = blockIdx.y * BM;
    const int n0 = blockIdx.x * BN;
    const int wm = (w >> 2) * 64;
    const int wn = (w & 3) * 32;

    const int srow = tid >> 2;
    const int sseg = tid & 3;
    const size_t gA = (size_t)(m0 + srow) * KTOT + sseg * 8;
    const size_t gB = (size_t)(n0 + srow) * KTOT + sseg * 8;
    const size_t rstep = (size_t)64 * KTOT;
    const uint32_t soff0 = (uint32_t)(srow * ROWB + sseg * 16);
    const uint32_t soff1 = soff0 + 64 * ROWB;

    auto load_stage = [&](int kt, int stg) {
        const uint32_t s0 = sb + stg * STG_BYTES;
        const __nv_bfloat16* pa  = Ahi + gA + (size_t)kt * BK;
        const __nv_bfloat16* pal = Alo + gA + (size_t)kt * BK;
        const __nv_bfloat16* pb  = Bhi + gB + (size_t)kt * BK;
        const __nv_bfloat16* pbl = Blo + gB + (size_t)kt * BK;
        cp16(s0 + soff0, pa);             cp16(s0 + soff1, pa + rstep);
        cp16(s0 + OFF_ALO + soff0, pal);  cp16(s0 + OFF_ALO + soff1, pal + rstep);
        cp16(s0 + OFF_BHI + soff0, pb);   cp16(s0 + OFF_BHI + soff1, pb + rstep);
        cp16(s0 + OFF_BLO + soff0, pbl);  cp16(s0 + OFF_BLO + soff1, pbl + rstep);
    };

    float acc[4][4][4];
#pragma unroll
    for (int i = 0; i < 4; ++i)
#pragma unroll
        for (int j = 0; j < 4; ++j)
#pragma unroll
            for (int e = 0; e < 4; ++e) acc[i][j][e] = 0.f;

    const int ar = lane & 15, ah = lane >> 4;
    const uint32_t aoffb = (uint32_t)((wm + ar) * ROWB + ah * 16);
    const int grp = lane >> 3, l8 = lane & 7;
    const uint32_t boffb = (uint32_t)((wn + ((grp >> 1) << 3) + l8) * ROWB + (grp & 1) * 16);

    load_stage(0, 0);
    cp_commit();

    for (int kt = 0; kt < NKT; ++kt) {
        if (kt + 1 < NKT) {
            load_stage(kt + 1, (kt + 1) & 1);
            cp_commit();
            cp_wait<1>();
        } else {
            cp_wait<0>();
        }
        __syncthreads();

        const uint32_t s0 = sb + (kt & 1) * STG_BYTES;
#pragma unroll
        for (int ks = 0; ks < 2; ++ks) {
            const uint32_t akoff = s0 + aoffb + ks * 32;
            const uint32_t bkoff = s0 + OFF_BHI + boffb + ks * 32;

            uint32_t fah[4][4], fal[4][4];
#pragma unroll
            for (int mt = 0; mt < 4; ++mt) {
                ldsm4(akoff + mt * 16 * ROWB,
                      fah[mt][0], fah[mt][1], fah[mt][2], fah[mt][3]);
                ldsm4(akoff + OFF_ALO + mt * 16 * ROWB,
                      fal[mt][0], fal[mt][1], fal[mt][2], fal[mt][3]);
            }
            uint32_t fbh[8], fbl[8];
            ldsm4(bkoff,                         fbh[0], fbh[1], fbh[2], fbh[3]);
            ldsm4(bkoff + 16 * ROWB,             fbh[4], fbh[5], fbh[6], fbh[7]);
            ldsm4(bkoff + (OFF_BLO - OFF_BHI),   fbl[0], fbl[1], fbl[2], fbl[3]);
            ldsm4(bkoff + (OFF_BLO - OFF_BHI) + 16 * ROWB,
                                                 fbl[4], fbl[5], fbl[6], fbl[7]);

#pragma unroll
            for (int mt = 0; mt < 4; ++mt) {
#pragma unroll
                for (int nt = 0; nt < 4; ++nt) {
                    float* c = acc[mt][nt];
                    mma_bf16(c[0], c[1], c[2], c[3],
                             fah[mt][0], fah[mt][1], fah[mt][2], fah[mt][3],
                             fbh[nt * 2], fbh[nt * 2 + 1]);
                    mma_bf16(c[0], c[1], c[2], c[3],
                             fah[mt][0], fah[mt][1], fah[mt][2], fah[mt][3],
                             fbl[nt * 2], fbl[nt * 2 + 1]);
                    mma_bf16(c[0], c[1], c[2], c[3],
                             fal[mt][0], fal[mt][1], fal[mt][2], fal[mt][3],
                             fbh[nt * 2], fbh[nt * 2 + 1]);
                }
            }
        }
        __syncthreads();
    }

    // epilogue
    const int erow = (lane >> 2);
    const int ecol = (lane & 3) * 2;
#pragma unroll
    for (int mt = 0; mt < 4; ++mt) {
#pragma unroll
        for (int nt = 0; nt < 4; ++nt) {
#pragma unroll
            for (int half = 0; half < 2; ++half) {
                const int row = m0 + wm + mt * 16 + erow + half * 8;
                const int col = n0 + wn + nt * 8 + ecol;
                float v0 = acc[mt][nt][half * 2 + 0] + bias[col];
                float v1 = acc[mt][nt][half * 2 + 1] + bias[col + 1];
                if (mode == 0) {
                    const int bb = row >> 11, s = row & 2047;
                    const int part = col >> 10;
                    const int dd = col & 1023;
                    const int h = dd >> 6, hd = dd & 63;
                    const int bh = (bb << 4) + h;
                    if (part == 0) { v0 *= 0.125f; v1 *= 0.125f; }
                    __nv_bfloat16 h0, l0, h1, l1;
                    split2(v0, h0, l0); split2(v1, h1, l1);
                    if (part == 2) {
                        const size_t base = ((size_t)bh * DHEAD + hd) * SEQ + s;
                        s_vt_hi[base] = h0;       s_vt_lo[base] = l0;
                        s_vt_hi[base + SEQ] = h1; s_vt_lo[base + SEQ] = l1;
                    } else {
                        const size_t base = ((size_t)bh * SEQ + s) * DHEAD + hd;
                        __nv_bfloat16* dh_ = (part == 0) ? s_q_hi : s_k_hi;
                        __nv_bfloat16* dl_ = (part == 0) ? s_q_lo : s_k_lo;
                        *(uint32_t*)(dh_ + base) = packbf(h0, h1);
                        *(uint32_t*)(dl_ + base) = packbf(l0, l1);
                    }
                } else {
                    *(float2*)(outp + (size_t)row * DIM + col) = make_float2(v0, v1);
                }
            }
        }
    }
}

// ---------------------------------------------------------------------------
// Tensor-core flash attention (bf16 split-2, fp32 softmax) with cp.async
// 2-stage KV pipeline. CTA: 128 q rows x one (b,h); 4 warps; KV tiles of 64.
// ---------------------------------------------------------------------------
#define AROWB 144
#define AQ_H 0
#define AQ_L 18432
#define AKV0 36864
#define AKV_STG 36864
#define AK_L 9216
#define AV_H 18432
#define AV_L 27648
#define ASM_BYTES (AKV0 + 2 * AKV_STG)   // 110592

__global__ __launch_bounds__(128) void attn_tc_kernel()
{
    extern __shared__ char asmem[];
    const uint32_t sb = smem_u32(asmem);
    const int tid  = threadIdx.x;
    const int w    = tid >> 5;
    const int lane = tid & 31;
    const int qt   = blockIdx.x;
    const int bh   = blockIdx.y;
    const int q0   = qt * 128;

    const __nv_bfloat16* Qh = s_q_hi + (size_t)bh * SEQ * DHEAD;
    const __nv_bfloat16* Ql = s_q_lo + (size_t)bh * SEQ * DHEAD;
    const __nv_bfloat16* Kh = s_k_hi + (size_t)bh * SEQ * DHEAD;
    const __nv_bfloat16* Kl = s_k_lo + (size_t)bh * SEQ * DHEAD;
    const __nv_bfloat16* Vh = s_vt_hi + (size_t)bh * DHEAD * SEQ;
    const __nv_bfloat16* Vl = s_vt_lo + (size_t)bh * DHEAD * SEQ;

    auto load_kv = [&](int kt, int stg) {
        const uint32_t s0 = sb + AKV0 + stg * AKV_STG;
        const int kv0 = kt * 64;
#pragma unroll
        for (int i = 0; i < 4; ++i) {
            const int c = tid + i * 128;
            const int row = c >> 3, seg = c & 7;
            const uint32_t so = row * AROWB + seg * 16;
            const size_t gk = (size_t)(kv0 + row) * DHEAD + seg * 8;
            const size_t gv = (size_t)row * SEQ + kv0 + seg * 8;
            cp16(s0 + so, Kh + gk);
            cp16(s0 + AK_L + so, Kl + gk);
            cp16(s0 + AV_H + so, Vh + gv);
            cp16(s0 + AV_L + so, Vl + gv);
        }
    };

    // Q tile (128 rows x 64 bf16) hi/lo — plain stores, covered by first barrier
#pragma unroll
    for (int i = 0; i < 8; ++i) {
        const int c = tid + i * 128;
        const int row = c >> 3, seg = c & 7;
        const uint32_t so = row * AROWB + seg * 16;
        const size_t go = (size_t)(q0 + row) * DHEAD + seg * 8;
        *(uint4*)(asmem + AQ_H + so) = *(const uint4*)(Qh + go);
        *(uint4*)(asmem + AQ_L + so) = *(const uint4*)(Ql + go);
    }

    const int ar = lane & 15, ahh = lane >> 4;
    const int grp = lane >> 3, l8 = lane & 7;
    const int row0 = lane >> 2, coll = (lane & 3) * 2;

    float m_run[4], l_run[4];
#pragma unroll
    for (int i = 0; i < 4; ++i) { m_run[i] = -1e30f; l_run[i] = 0.f; }
    float oacc[2][8][4];
#pragma unroll
    for (int mt = 0; mt < 2; ++mt)
#pragma unroll
        for (int nt = 0; nt < 8; ++nt)
#pragma unroll
            for (int e = 0; e < 4; ++e) oacc[mt][nt][e] = 0.f;

    const int ntiles = qt * 2 + 2;
    load_kv(0, 0);
    cp_commit();

    for (int kt = 0; kt < ntiles; ++kt) {
        if (kt + 1 < ntiles) {
            load_kv(kt + 1, (kt + 1) & 1);
            cp_commit();
            cp_wait<1>();
        } else {
            cp_wait<0>();
        }
        __syncthreads();

        const uint32_t kvb = sb + AKV0 + (kt & 1) * AKV_STG;
        const int kv0 = kt * 64;

        // ---- scores: S = Q K^T (split-2) ----
        float s[2][8][4];
#pragma unroll
        for (int mt = 0; mt < 2; ++mt)
#pragma unroll
            for (int nt = 0; nt < 8; ++nt)
#pragma unroll
                for (int e = 0; e < 4; ++e) s[mt][nt][e] = 0.f;

#pragma unroll
        for (int ks = 0; ks < 4; ++ks) {
            uint32_t kbh[4][4], kbl[4][4];
#pragma unroll
            for (int nb = 0; nb < 4; ++nb) {
                const uint32_t bo = (uint32_t)(((grp >> 1) * 8 + l8 + nb * 16) * AROWB +
                                               (grp & 1) * 16 + ks * 32);
                ldsm4(kvb + bo, kbh[nb][0], kbh[nb][1], kbh[nb][2], kbh[nb][3]);
                ldsm4(kvb + AK_L + bo, kbl[nb][0], kbl[nb][1], kbl[nb][2], kbl[nb][3]);
            }
#pragma unroll
            for (int mt = 0; mt < 2; ++mt) {
                const uint32_t ao = (uint32_t)((w * 32 + mt * 16 + ar) * AROWB +
                                               ahh * 16 + ks * 32);
                uint32_t qh0, qh1, qh2, qh3, ql0, ql1, ql2, ql3;
                ldsm4(sb + AQ_H + ao, qh0, qh1, qh2, qh3);
                ldsm4(sb + AQ_L + ao, ql0, ql1, ql2, ql3);
#pragma unroll
                for (int nt = 0; nt < 8; ++nt) {
                    float* c = s[mt][nt];
                    const int nb = nt >> 1, p = nt & 1;
                    mma_bf16(c[0], c[1], c[2], c[3], qh0, qh1, qh2, qh3,
                             kbh[nb][p * 2], kbh[nb][p * 2 + 1]);
                    mma_bf16(c[0], c[1], c[2], c[3], qh0, qh1, qh2, qh3,
                             kbl[nb][p * 2], kbl[nb][p * 2 + 1]);
                    mma_bf16(c[0], c[1], c[2], c[3], ql0, ql1, ql2, ql3,
                             kbh[nb][p * 2], kbh[nb][p * 2 + 1]);
                }
            }
        }

        // ---- causal mask ----
        if (kt >= qt * 2) {
#pragma unroll
            for (int mt = 0; mt < 2; ++mt) {
                const int rbase = q0 + w * 32 + mt * 16 + row0;
#pragma unroll
                for (int nt = 0; nt < 8; ++nt) {
                    const int cb = kv0 + nt * 8 + coll;
                    if (cb > rbase)     s[mt][nt][0] = -10000.f;
                    if (cb + 1 > rbase) s[mt][nt][1] = -10000.f;
                    if (cb > rbase + 8)     s[mt][nt][2] = -10000.f;
                    if (cb + 1 > rbase + 8) s[mt][nt][3] = -10000.f;
                }
            }
        }

        // ---- online softmax ----
        float corr[4];
#pragma unroll
        for (int slot = 0; slot < 4; ++slot) {
            const int mt = slot >> 1, h2 = slot & 1;
            float tm = -1e30f;
#pragma unroll
            for (int nt = 0; nt < 8; ++nt)
                tm = fmaxf(tm, fmaxf(s[mt][nt][h2 * 2], s[mt][nt][h2 * 2 + 1]));
            tm = fmaxf(tm, __shfl_xor_sync(0xffffffffu, tm, 1));
            tm = fmaxf(tm, __shfl_xor_sync(0xffffffffu, tm, 2));
            const float mnew = fmaxf(m_run[slot], tm);
            corr[slot] = __expf(m_run[slot] - mnew);
            m_run[slot] = mnew;
            l_run[slot] *= corr[slot];
        }
#pragma unroll
        for (int mt = 0; mt < 2; ++mt)
#pragma unroll
            for (int nt = 0; nt < 8; ++nt) {
                oacc[mt][nt][0] *= corr[mt * 2];
                oacc[mt][nt][1] *= corr[mt * 2];
                oacc[mt][nt][2] *= corr[mt * 2 + 1];
                oacc[mt][nt][3] *= corr[mt * 2 + 1];
            }

        // ---- P = exp(S - m), split-2 pack into A fragments ----
        uint32_t ph[2][8][2], pl[2][8][2];
#pragma unroll
        for (int mt = 0; mt < 2; ++mt)
#pragma unroll
            for (int nt = 0; nt < 8; ++nt) {
                const float p0 = __expf(s[mt][nt][0] - m_run[mt * 2]);
                const float p1 = __expf(s[mt][nt][1] - m_run[mt * 2]);
                const float p2 = __expf(s[mt][nt][2] - m_run[mt * 2 + 1]);
                const float p3 = __expf(s[mt][nt][3] - m_run[mt * 2 + 1]);
                l_run[mt * 2]     += p0 + p1;
                l_run[mt * 2 + 1] += p2 + p3;
                __nv_bfloat16 h0, lo0, h1, lo1, h2, lo2, h3, lo3;
                split2(p0, h0, lo0); split2(p1, h1, lo1);
                split2(p2, h2, lo2); split2(p3, h3, lo3);
                ph[mt][nt][0] = packbf(h0, h1);   ph[mt][nt][1] = packbf(h2, h3);
                pl[mt][nt][0] = packbf(lo0, lo1); pl[mt][nt][1] = packbf(lo2, lo3);
            }

        // ---- O += P V (split-2) ----
#pragma unroll
        for (int ks = 0; ks < 4; ++ks) {
            uint32_t vbh[4][4], vbl[4][4];
#pragma unroll
            for (int nb = 0; nb < 4; ++nb) {
                const uint32_t bo = (uint32_t)(((grp >> 1) * 8 + l8 + nb * 16) * AROWB +
                                               (grp & 1) * 16 + ks * 32);
                ldsm4(kvb + AV_H + bo, vbh[nb][0], vbh[nb][1], vbh[nb][2], vbh[nb][3]);
                ldsm4(kvb + AV_L + bo, vbl[nb][0], vbl[nb][1], vbl[nb][2], vbl[nb][3]);
            }
#pragma unroll
            for (int mt = 0; mt < 2; ++mt) {
                const uint32_t a0h = ph[mt][ks * 2][0],     a1h = ph[mt][ks * 2][1];
                const uint32_t a2h = ph[mt][ks * 2 + 1][0], a3h = ph[mt][ks * 2 + 1][1];
                const uint32_t a0l = pl[mt][ks * 2][0],     a1l = pl[mt][ks * 2][1];
                const uint32_t a2l = pl[mt][ks * 2 + 1][0], a3l = pl[mt][ks * 2 + 1][1];
#pragma unroll
                for (int nt = 0; nt < 8; ++nt) {
                    float* c = oacc[mt][nt];
                    const int nb = nt >> 1, p = nt & 1;
                    mma_bf16(c[0], c[1], c[2], c[3], a0h, a1h, a2h, a3h,
                             vbh[nb][p * 2], vbh[nb][p * 2 + 1]);
                    mma_bf16(c[0], c[1], c[2], c[3], a0h, a1h, a2h, a3h,
                             vbl[nb][p * 2], vbl[nb][p * 2 + 1]);
                    mma_bf16(c[0], c[1], c[2], c[3], a0l, a1l, a2l, a3l,
                             vbh[nb][p * 2], vbh[nb][p * 2 + 1]);
                }
            }
        }
        __syncthreads();
    }

    // ---- finalize ----
    float inv[4];
#pragma unroll
    for (int slot = 0; slot < 4; ++slot) {
        float lt = l_run[slot];
        lt += __shfl_xor_sync(0xffffffffu, lt, 1);
        lt += __shfl_xor_sync(0xffffffffu, lt, 2);
        inv[slot] = 1.f / lt;
    }
    const int b = bh >> 4, h = bh & 15;
#pragma unroll
    for (int mt = 0; mt < 2; ++mt) {
#pragma unroll
        for (int half = 0; half < 2; ++half) {
            const size_t orow = (size_t)b * SEQ + q0 + w * 32 + mt * 16 + row0 + half * 8;
            const float iv = inv[mt * 2 + half];
#pragma unroll
            for (int nt = 0; nt < 8; ++nt) {
                const int col = h * DHEAD + nt * 8 + coll;
                const float v0 = oacc[mt][nt][half * 2 + 0] * iv;
                const float v1 = oacc[mt][nt][half * 2 + 1] * iv;
                __nv_bfloat16 h0, l0, h1, l1;
                split2(v0, h0, l0); split2(v1, h1, l1);
                *(uint32_t*)(s_a_hi + orow * DIM + col) = packbf(h0, h1);
                *(uint32_t*)(s_a_lo + orow * DIM + col) = packbf(l0, l1);
            }
        }
    }
}

// ---------------------------------------------------------------------------
extern "C" void kernel_launch(void* const* d_in, const int* in_sizes, int n_in,
                              void* d_out, int out_size)
{
    const float* x      = (const float*)d_in[0];
    const float* w_attn = (const float*)d_in[1];
    const float* b_attn = (const float*)d_in[2];
    const float* w_proj = (const float*)d_in[3];
    const float* b_proj = (const float*)d_in[4];
    float* out = (float*)d_out;

    __nv_bfloat16 *xa_hi, *xa_lo, *wq_hi, *wq_lo, *wp_hi, *wp_lo;
    cudaGetSymbolAddress((void**)&xa_hi, s_a_hi);
    cudaGetSymbolAddress((void**)&xa_lo, s_a_lo);
    cudaGetSymbolAddress((void**)&wq_hi, s_wq_hi);
    cudaGetSymbolAddress((void**)&wq_lo, s_wq_lo);
    cudaGetSymbolAddress((void**)&wp_hi, s_wp_hi);
    cudaGetSymbolAddress((void**)&wp_lo, s_wp_lo);

    cudaFuncSetAttribute(tc_gemm_kernel,
                         cudaFuncAttributeMaxDynamicSharedMemorySize, GSM_BYTES);
    cudaFuncSetAttribute(attn_tc_kernel,
                         cudaFuncAttributeMaxDynamicSharedMemorySize, ASM_BYTES);

    // 1) split x -> bf16 hi/lo
    split_kernel<<<(MROWS * KTOT / 4 + 255) / 256, 256>>>(x, xa_hi, xa_lo, MROWS * KTOT / 4);
    // 2) transpose+split weights
    transp_split_kernel<<<dim3(NQKV / 32, KTOT / 32), dim3(32, 8)>>>(w_attn, KTOT, NQKV, wq_hi, wq_lo);
    transp_split_kernel<<<dim3(DIM / 32, KTOT / 32), dim3(32, 8)>>>(w_proj, KTOT, DIM, wp_hi, wp_lo);
    // 3) QKV GEMM -> bf16 split q/k/vt
    tc_gemm_kernel<<<dim3(NQKV / BN, MROWS / BM), 256, GSM_BYTES>>>(
        xa_hi, xa_lo, wq_hi, wq_lo, b_attn, nullptr, 0);
    // 4) tensor-core flash attention -> writes s_a_hi/s_a_lo
    attn_tc_kernel<<<dim3(SEQ / 128, BATCH * NHEAD), 128, ASM_BYTES>>>();
    // 5) output projection
    tc_gemm_kernel<<<dim3(DIM / BN, MROWS / BM), 256, GSM_BYTES>>>(
        xa_hi, xa_lo, wp_hi, wp_lo, b_proj, out, 1);
}

// round 7
// speedup vs baseline: 1.0977x; 1.0977x over previous
#include <cuda_runtime.h>
#include <cuda_bf16.h>
#include <cstdint>

// Problem shape (fixed by the dataset)
#define BATCH 2
#define SEQ   2048
#define DIM   1024
#define NHEAD 16
#define DHEAD 64
#define MROWS (BATCH * SEQ)          // 4096
#define NQKV  (3 * DIM)              // 3072
#define KTOT  1024

// ---------------------------------------------------------------------------
// Scratch (allocation-free rule: __device__ globals), all bf16 split-2 pairs
// ---------------------------------------------------------------------------
__device__ __nv_bfloat16 s_a_hi[MROWS * KTOT];   // GEMM A: x, then attention out
__device__ __nv_bfloat16 s_a_lo[MROWS * KTOT];
__device__ __nv_bfloat16 s_wq_hi[NQKV * KTOT];   // w_attn^T [3072,1024]
__device__ __nv_bfloat16 s_wq_lo[NQKV * KTOT];
__device__ __nv_bfloat16 s_wp_hi[DIM * KTOT];    // w_proj^T [1024,1024]
__device__ __nv_bfloat16 s_wp_lo[DIM * KTOT];
// attention operands, written by QKV epilogue
__device__ __nv_bfloat16 s_q_hi[BATCH * NHEAD * SEQ * DHEAD];  // [bh,s,dh], q*0.125
__device__ __nv_bfloat16 s_q_lo[BATCH * NHEAD * SEQ * DHEAD];
__device__ __nv_bfloat16 s_k_hi[BATCH * NHEAD * SEQ * DHEAD];  // [bh,s,dh]
__device__ __nv_bfloat16 s_k_lo[BATCH * NHEAD * SEQ * DHEAD];
__device__ __nv_bfloat16 s_vt_hi[BATCH * NHEAD * DHEAD * SEQ]; // [bh,dh,s]
__device__ __nv_bfloat16 s_vt_lo[BATCH * NHEAD * DHEAD * SEQ];

// ---------------------------------------------------------------------------
// PTX helpers (baseline ISA — compiles for sm_103)
// ---------------------------------------------------------------------------
__device__ __forceinline__ uint32_t smem_u32(const void* p) {
    uint32_t a;
    asm("{ .reg .u64 t; cvta.to.shared.u64 t, %1; cvt.u32.u64 %0, t; }"
        : "=r"(a) : "l"(p));
    return a;
}
__device__ __forceinline__ void ldsm4(uint32_t addr, uint32_t& r0, uint32_t& r1,
                                      uint32_t& r2, uint32_t& r3) {
    asm volatile("ldmatrix.sync.aligned.m8n8.x4.shared.b16 {%0,%1,%2,%3}, [%4];"
                 : "=r"(r0), "=r"(r1), "=r"(r2), "=r"(r3) : "r"(addr));
}
__device__ __forceinline__ void mma_bf16(float& c0, float& c1, float& c2, float& c3,
                                         uint32_t a0, uint32_t a1, uint32_t a2, uint32_t a3,
                                         uint32_t b0, uint32_t b1) {
    asm volatile("mma.sync.aligned.m16n8k16.row.col.f32.bf16.bf16.f32 "
                 "{%0,%1,%2,%3}, {%4,%5,%6,%7}, {%8,%9}, {%0,%1,%2,%3};"
                 : "+f"(c0), "+f"(c1), "+f"(c2), "+f"(c3)
                 : "r"(a0), "r"(a1), "r"(a2), "r"(a3), "r"(b0), "r"(b1));
}
__device__ __forceinline__ void cp16(uint32_t saddr, const void* g) {
    asm volatile("cp.async.cg.shared.global [%0], [%1], 16;"
                 :: "r"(saddr), "l"(g) : "memory");
}
__device__ __forceinline__ void cp_commit() {
    asm volatile("cp.async.commit_group;" ::: "memory");
}
template <int N>
__device__ __forceinline__ void cp_wait() {
    asm volatile("cp.async.wait_group %0;" :: "n"(N) : "memory");
}
__device__ __forceinline__ void split2(float v, __nv_bfloat16& h, __nv_bfloat16& l) {
    h = __float2bfloat16_rn(v);
    l = __float2bfloat16_rn(v - __bfloat162float(h));
}
__device__ __forceinline__ uint32_t packbf(__nv_bfloat16 a, __nv_bfloat16 b) {
    return (uint32_t)__bfloat16_as_ushort(a) | ((uint32_t)__bfloat16_as_ushort(b) << 16);
}

// ---------------------------------------------------------------------------
// Prep kernels
// ---------------------------------------------------------------------------
__global__ __launch_bounds__(256) void split_kernel(
    const float* __restrict__ src, __nv_bfloat16* __restrict__ hi,
    __nv_bfloat16* __restrict__ lo, int n4)
{
    int i = blockIdx.x * 256 + threadIdx.x;
    if (i >= n4) return;
    float4 v = ((const float4*)src)[i];
    __nv_bfloat16 h0, l0, h1, l1, h2, l2, h3, l3;
    split2(v.x, h0, l0); split2(v.y, h1, l1);
    split2(v.z, h2, l2); split2(v.w, h3, l3);
    uint2 uh = make_uint2(packbf(h0, h1), packbf(h2, h3));
    uint2 ul = make_uint2(packbf(l0, l1), packbf(l2, l3));
    *(uint2*)(hi + (size_t)i * 4) = uh;
    *(uint2*)(lo + (size_t)i * 4) = ul;
}

__global__ __launch_bounds__(256) void transp_split_kernel(
    const float* __restrict__ w, int K, int N,
    __nv_bfloat16* __restrict__ out_hi, __nv_bfloat16* __restrict__ out_lo)
{
    __shared__ float t[32][33];
    const int tx = threadIdx.x, ty = threadIdx.y;
    const int n0 = blockIdx.x * 32, k0 = blockIdx.y * 32;
#pragma unroll
    for (int i = 0; i < 4; ++i)
        t[ty + i * 8][tx] = w[(size_t)(k0 + ty + i * 8) * N + n0 + tx];
    __syncthreads();
#pragma unroll
    for (int i = 0; i < 4; ++i) {
        const int n = n0 + ty + i * 8;
        float v = t[tx][ty + i * 8];
        __nv_bfloat16 h, l;
        split2(v, h, l);
        out_hi[(size_t)n * K + k0 + tx] = h;
        out_lo[(size_t)n * K + k0 + tx] = l;
    }
}

// ---------------------------------------------------------------------------
// HMMA GEMM, cp.async 2-stage, 2 CTAs/SM (the R7 change).
// D[M,N] = A @ B^T + bias, bf16 split-2 (3 products, fp32 accum).
// mode 0: QKV epilogue -> bf16 split q/k (k-major) and vt (transposed)
// mode 1: plain fp32 out
// ---------------------------------------------------------------------------
#define BM 128
#define BN 128
#define BK 32
#define ROWB 80
#define NKT (KTOT / BK)          // 32
#define OFF_ALO 10240
#define OFF_BHI 20480
#define OFF_BLO 30720
#define STG_BYTES 40960
#define GSM_BYTES (2 * STG_BYTES)   // 81920 per CTA; x2 CTAs = 160KB/SM

__global__ __launch_bounds__(256, 2) void tc_gemm_kernel(
    const __nv_bfloat16* __restrict__ Ahi, const __nv_bfloat16* __restrict__ Alo,
    const __nv_bfloat16* __restrict__ Bhi, const __nv_bfloat16* __restrict__ Blo,
    const float* __restrict__ bias, float* __restrict__ outp, int mode)
{
    extern __shared__ char gsm[];
    const uint32_t sb = smem_u32(gsm);

    const int tid  = threadIdx.x;
    const int w    = tid >> 5;
    const int lane = tid & 31;
    const int m0 = blockIdx.y * BM;
    const int n0 = blockIdx.x * BN;
    const int wm = (w >> 2) * 64;
    const int wn = (w & 3) * 32;

    const int srow = tid >> 2;
    const int sseg = tid & 3;
    const size_t gA = (size_t)(m0 + srow) * KTOT + sseg * 8;
    const size_t gB = (size_t)(n0 + srow) * KTOT + sseg * 8;
    const size_t rstep = (size_t)64 * KTOT;
    const uint32_t soff0 = (uint32_t)(srow * ROWB + sseg * 16);
    const uint32_t soff1 = soff0 + 64 * ROWB;

    auto load_stage = [&](int kt, int stg) {
        const uint32_t s0 = sb + stg * STG_BYTES;
        const __nv_bfloat16* pa  = Ahi + gA + (size_t)kt * BK;
        const __nv_bfloat16* pal = Alo + gA + (size_t)kt * BK;
        const __nv_bfloat16* pb  = Bhi + gB + (size_t)kt * BK;
        const __nv_bfloat16* pbl = Blo + gB + (size_t)kt * BK;
        cp16(s0 + soff0, pa);             cp16(s0 + soff1, pa + rstep);
        cp16(s0 + OFF_ALO + soff0, pal);  cp16(s0 + OFF_ALO + soff1, pal + rstep);
        cp16(s0 + OFF_BHI + soff0, pb);   cp16(s0 + OFF_BHI + soff1, pb + rstep);
        cp16(s0 + OFF_BLO + soff0, pbl);  cp16(s0 + OFF_BLO + soff1, pbl + rstep);
    };

    float acc[4][4][4];
#pragma unroll
    for (int i = 0; i < 4; ++i)
#pragma unroll
        for (int j = 0; j < 4; ++j)
#pragma unroll
            for (int e = 0; e < 4; ++e) acc[i][j][e] = 0.f;

    const int ar = lane & 15, ah = lane >> 4;
    const uint32_t aoffb = (uint32_t)((wm + ar) * ROWB + ah * 16);
    const int grp = lane >> 3, l8 = lane & 7;
    const uint32_t boffb = (uint32_t)((wn + ((grp >> 1) << 3) + l8) * ROWB + (grp & 1) * 16);

    load_stage(0, 0);
    cp_commit();

    for (int kt = 0; kt < NKT; ++kt) {
        if (kt + 1 < NKT) {
            load_stage(kt + 1, (kt + 1) & 1);
            cp_commit();
            cp_wait<1>();
        } else {
            cp_wait<0>();
        }
        __syncthreads();

        const uint32_t s0 = sb + (kt & 1) * STG_BYTES;
#pragma unroll
        for (int ks = 0; ks < 2; ++ks) {
            const uint32_t akoff = s0 + aoffb + ks * 32;
            const uint32_t bkoff = s0 + OFF_BHI + boffb + ks * 32;

            uint32_t fah[4][4], fal[4][4];
#pragma unroll
            for (int mt = 0; mt < 4; ++mt) {
                ldsm4(akoff + mt * 16 * ROWB,
                      fah[mt][0], fah[mt][1], fah[mt][2], fah[mt][3]);
                ldsm4(akoff + OFF_ALO + mt * 16 * ROWB,
                      fal[mt][0], fal[mt][1], fal[mt][2], fal[mt][3]);
            }
            uint32_t fbh[8], fbl[8];
            ldsm4(bkoff,                         fbh[0], fbh[1], fbh[2], fbh[3]);
            ldsm4(bkoff + 16 * ROWB,             fbh[4], fbh[5], fbh[6], fbh[7]);
            ldsm4(bkoff + (OFF_BLO - OFF_BHI),   fbl[0], fbl[1], fbl[2], fbl[3]);
            ldsm4(bkoff + (OFF_BLO - OFF_BHI) + 16 * ROWB,
                                                 fbl[4], fbl[5], fbl[6], fbl[7]);

#pragma unroll
            for (int mt = 0; mt < 4; ++mt) {
#pragma unroll
                for (int nt = 0; nt < 4; ++nt) {
                    float* c = acc[mt][nt];
                    mma_bf16(c[0], c[1], c[2], c[3],
                             fah[mt][0], fah[mt][1], fah[mt][2], fah[mt][3],
                             fbh[nt * 2], fbh[nt * 2 + 1]);
                    mma_bf16(c[0], c[1], c[2], c[3],
                             fah[mt][0], fah[mt][1], fah[mt][2], fah[mt][3],
                             fbl[nt * 2], fbl[nt * 2 + 1]);
                    mma_bf16(c[0], c[1], c[2], c[3],
                             fal[mt][0], fal[mt][1], fal[mt][2], fal[mt][3],
                             fbh[nt * 2], fbh[nt * 2 + 1]);
                }
            }
        }
        __syncthreads();
    }

    // epilogue
    const int erow = (lane >> 2);
    const int ecol = (lane & 3) * 2;
#pragma unroll
    for (int mt = 0; mt < 4; ++mt) {
#pragma unroll
        for (int nt = 0; nt < 4; ++nt) {
#pragma unroll
            for (int half = 0; half < 2; ++half) {
                const int row = m0 + wm + mt * 16 + erow + half * 8;
                const int col = n0 + wn + nt * 8 + ecol;
                float v0 = acc[mt][nt][half * 2 + 0] + bias[col];
                float v1 = acc[mt][nt][half * 2 + 1] + bias[col + 1];
                if (mode == 0) {
                    const int bb = row >> 11, s = row & 2047;
                    const int part = col >> 10;
                    const int dd = col & 1023;
                    const int h = dd >> 6, hd = dd & 63;
                    const int bh = (bb << 4) + h;
                    if (part == 0) { v0 *= 0.125f; v1 *= 0.125f; }
                    __nv_bfloat16 h0, l0, h1, l1;
                    split2(v0, h0, l0); split2(v1, h1, l1);
                    if (part == 2) {
                        const size_t base = ((size_t)bh * DHEAD + hd) * SEQ + s;
                        s_vt_hi[base] = h0;       s_vt_lo[base] = l0;
                        s_vt_hi[base + SEQ] = h1; s_vt_lo[base + SEQ] = l1;
                    } else {
                        const size_t base = ((size_t)bh * SEQ + s) * DHEAD + hd;
                        __nv_bfloat16* dh_ = (part == 0) ? s_q_hi : s_k_hi;
                        __nv_bfloat16* dl_ = (part == 0) ? s_q_lo : s_k_lo;
                        *(uint32_t*)(dh_ + base) = packbf(h0, h1);
                        *(uint32_t*)(dl_ + base) = packbf(l0, l1);
                    }
                } else {
                    *(float2*)(outp + (size_t)row * DIM + col) = make_float2(v0, v1);
                }
            }
        }
    }
}

// ---------------------------------------------------------------------------
// Tensor-core flash attention (bf16 split-2, fp32 softmax) with cp.async
// 2-stage KV pipeline. CTA: 128 q rows x one (b,h); 4 warps; KV tiles of 64.
// (unchanged from R6)
// ---------------------------------------------------------------------------
#define AROWB 144
#define AQ_H 0
#define AQ_L 18432
#define AKV0 36864
#define AKV_STG 36864
#define AK_L 9216
#define AV_H 18432
#define AV_L 27648
#define ASM_BYTES (AKV0 + 2 * AKV_STG)   // 110592

__global__ __launch_bounds__(128) void attn_tc_kernel()
{
    extern __shared__ char asmem[];
    const uint32_t sb = smem_u32(asmem);
    const int tid  = threadIdx.x;
    const int w    = tid >> 5;
    const int lane = tid & 31;
    const int qt   = blockIdx.x;
    const int bh   = blockIdx.y;
    const int q0   = qt * 128;

    const __nv_bfloat16* Qh = s_q_hi + (size_t)bh * SEQ * DHEAD;
    const __nv_bfloat16* Ql = s_q_lo + (size_t)bh * SEQ * DHEAD;
    const __nv_bfloat16* Kh = s_k_hi + (size_t)bh * SEQ * DHEAD;
    const __nv_bfloat16* Kl = s_k_lo + (size_t)bh * SEQ * DHEAD;
    const __nv_bfloat16* Vh = s_vt_hi + (size_t)bh * DHEAD * SEQ;
    const __nv_bfloat16* Vl = s_vt_lo + (size_t)bh * DHEAD * SEQ;

    auto load_kv = [&](int kt, int stg) {
        const uint32_t s0 = sb + AKV0 + stg * AKV_STG;
        const int kv0 = kt * 64;
#pragma unroll
        for (int i = 0; i < 4; ++i) {
            const int c = tid + i * 128;
            const int row = c >> 3, seg = c & 7;
            const uint32_t so = row * AROWB + seg * 16;
            const size_t gk = (size_t)(kv0 + row) * DHEAD + seg * 8;
            const size_t gv = (size_t)row * SEQ + kv0 + seg * 8;
            cp16(s0 + so, Kh + gk);
            cp16(s0 + AK_L + so, Kl + gk);
            cp16(s0 + AV_H + so, Vh + gv);
            cp16(s0 + AV_L + so, Vl + gv);
        }
    };

    // Q tile (128 rows x 64 bf16) hi/lo — plain stores, covered by first barrier
#pragma unroll
    for (int i = 0; i < 8; ++i) {
        const int c = tid + i * 128;
        const int row = c >> 3, seg = c & 7;
        const uint32_t so = row * AROWB + seg * 16;
        const size_t go = (size_t)(q0 + row) * DHEAD + seg * 8;
        *(uint4*)(asmem + AQ_H + so) = *(const uint4*)(Qh + go);
        *(uint4*)(asmem + AQ_L + so) = *(const uint4*)(Ql + go);
    }

    const int ar = lane & 15, ahh = lane >> 4;
    const int grp = lane >> 3, l8 = lane & 7;
    const int row0 = lane >> 2, coll = (lane & 3) * 2;

    float m_run[4], l_run[4];
#pragma unroll
    for (int i = 0; i < 4; ++i) { m_run[i] = -1e30f; l_run[i] = 0.f; }
    float oacc[2][8][4];
#pragma unroll
    for (int mt = 0; mt < 2; ++mt)
#pragma unroll
        for (int nt = 0; nt < 8; ++nt)
#pragma unroll
            for (int e = 0; e < 4; ++e) oacc[mt][nt][e] = 0.f;

    const int ntiles = qt * 2 + 2;
    load_kv(0, 0);
    cp_commit();

    for (int kt = 0; kt < ntiles; ++kt) {
        if (kt + 1 < ntiles) {
            load_kv(kt + 1, (kt + 1) & 1);
            cp_commit();
            cp_wait<1>();
        } else {
            cp_wait<0>();
        }
        __syncthreads();

        const uint32_t kvb = sb + AKV0 + (kt & 1) * AKV_STG;
        const int kv0 = kt * 64;

        // ---- scores: S = Q K^T (split-2) ----
        float s[2][8][4];
#pragma unroll
        for (int mt = 0; mt < 2; ++mt)
#pragma unroll
            for (int nt = 0; nt < 8; ++nt)
#pragma unroll
                for (int e = 0; e < 4; ++e) s[mt][nt][e] = 0.f;

#pragma unroll
        for (int ks = 0; ks < 4; ++ks) {
            uint32_t kbh[4][4], kbl[4][4];
#pragma unroll
            for (int nb = 0; nb < 4; ++nb) {
                const uint32_t bo = (uint32_t)(((grp >> 1) * 8 + l8 + nb * 16) * AROWB +
                                               (grp & 1) * 16 + ks * 32);
                ldsm4(kvb + bo, kbh[nb][0], kbh[nb][1], kbh[nb][2], kbh[nb][3]);
                ldsm4(kvb + AK_L + bo, kbl[nb][0], kbl[nb][1], kbl[nb][2], kbl[nb][3]);
            }
#pragma unroll
            for (int mt = 0; mt < 2; ++mt) {
                const uint32_t ao = (uint32_t)((w * 32 + mt * 16 + ar) * AROWB +
                                               ahh * 16 + ks * 32);
                uint32_t qh0, qh1, qh2, qh3, ql0, ql1, ql2, ql3;
                ldsm4(sb + AQ_H + ao, qh0, qh1, qh2, qh3);
                ldsm4(sb + AQ_L + ao, ql0, ql1, ql2, ql3);
#pragma unroll
                for (int nt = 0; nt < 8; ++nt) {
                    float* c = s[mt][nt];
                    const int nb = nt >> 1, p = nt & 1;
                    mma_bf16(c[0], c[1], c[2], c[3], qh0, qh1, qh2, qh3,
                             kbh[nb][p * 2], kbh[nb][p * 2 + 1]);
                    mma_bf16(c[0], c[1], c[2], c[3], qh0, qh1, qh2, qh3,
                             kbl[nb][p * 2], kbl[nb][p * 2 + 1]);
                    mma_bf16(c[0], c[1], c[2], c[3], ql0, ql1, ql2, ql3,
                             kbh[nb][p * 2], kbh[nb][p * 2 + 1]);
                }
            }
        }

        // ---- causal mask ----
        if (kt >= qt * 2) {
#pragma unroll
            for (int mt = 0; mt < 2; ++mt) {
                const int rbase = q0 + w * 32 + mt * 16 + row0;
#pragma unroll
                for (int nt = 0; nt < 8; ++nt) {
                    const int cb = kv0 + nt * 8 + coll;
                    if (cb > rbase)     s[mt][nt][0] = -10000.f;
                    if (cb + 1 > rbase) s[mt][nt][1] = -10000.f;
                    if (cb > rbase + 8)     s[mt][nt][2] = -10000.f;
                    if (cb + 1 > rbase + 8) s[mt][nt][3] = -10000.f;
                }
            }
        }

        // ---- online softmax ----
        float corr[4];
#pragma unroll
        for (int slot = 0; slot < 4; ++slot) {
            const int mt = slot >> 1, h2 = slot & 1;
            float tm = -1e30f;
#pragma unroll
            for (int nt = 0; nt < 8; ++nt)
                tm = fmaxf(tm, fmaxf(s[mt][nt][h2 * 2], s[mt][nt][h2 * 2 + 1]));
            tm = fmaxf(tm, __shfl_xor_sync(0xffffffffu, tm, 1));
            tm = fmaxf(tm, __shfl_xor_sync(0xffffffffu, tm, 2));
            const float mnew = fmaxf(m_run[slot], tm);
            corr[slot] = __expf(m_run[slot] - mnew);
            m_run[slot] = mnew;
            l_run[slot] *= corr[slot];
        }
#pragma unroll
        for (int mt = 0; mt < 2; ++mt)
#pragma unroll
            for (int nt = 0; nt < 8; ++nt) {
                oacc[mt][nt][0] *= corr[mt * 2];
                oacc[mt][nt][1] *= corr[mt * 2];
                oacc[mt][nt][2] *= corr[mt * 2 + 1];
                oacc[mt][nt][3] *= corr[mt * 2 + 1];
            }

        // ---- P = exp(S - m), split-2 pack into A fragments ----
        uint32_t ph[2][8][2], pl[2][8][2];
#pragma unroll
        for (int mt = 0; mt < 2; ++mt)
#pragma unroll
            for (int nt = 0; nt < 8; ++nt) {
                const float p0 = __expf(s[mt][nt][0] - m_run[mt * 2]);
                const float p1 = __expf(s[mt][nt][1] - m_run[mt * 2]);
                const float p2 = __expf(s[mt][nt][2] - m_run[mt * 2 + 1]);
                const float p3 = __expf(s[mt][nt][3] - m_run[mt * 2 + 1]);
                l_run[mt * 2]     += p0 + p1;
                l_run[mt * 2 + 1] += p2 + p3;
                __nv_bfloat16 h0, lo0, h1, lo1, h2, lo2, h3, lo3;
                split2(p0, h0, lo0); split2(p1, h1, lo1);
                split2(p2, h2, lo2); split2(p3, h3, lo3);
                ph[mt][nt][0] = packbf(h0, h1);   ph[mt][nt][1] = packbf(h2, h3);
                pl[mt][nt][0] = packbf(lo0, lo1); pl[mt][nt][1] = packbf(lo2, lo3);
            }

        // ---- O += P V (split-2) ----
#pragma unroll
        for (int ks = 0; ks < 4; ++ks) {
            uint32_t vbh[4][4], vbl[4][4];
#pragma unroll
            for (int nb = 0; nb < 4; ++nb) {
                const uint32_t bo = (uint32_t)(((grp >> 1) * 8 + l8 + nb * 16) * AROWB +
                                               (grp & 1) * 16 + ks * 32);
                ldsm4(kvb + AV_H + bo, vbh[nb][0], vbh[nb][1], vbh[nb][2], vbh[nb][3]);
                ldsm4(kvb + AV_L + bo, vbl[nb][0], vbl[nb][1], vbl[nb][2], vbl[nb][3]);
            }
#pragma unroll
            for (int mt = 0; mt < 2; ++mt) {
                const uint32_t a0h = ph[mt][ks * 2][0],     a1h = ph[mt][ks * 2][1];
                const uint32_t a2h = ph[mt][ks * 2 + 1][0], a3h = ph[mt][ks * 2 + 1][1];
                const uint32_t a0l = pl[mt][ks * 2][0],     a1l = pl[mt][ks * 2][1];
                const uint32_t a2l = pl[mt][ks * 2 + 1][0], a3l = pl[mt][ks * 2 + 1][1];
#pragma unroll
                for (int nt = 0; nt < 8; ++nt) {
                    float* c = oacc[mt][nt];
                    const int nb = nt >> 1, p = nt & 1;
                    mma_bf16(c[0], c[1], c[2], c[3], a0h, a1h, a2h, a3h,
                             vbh[nb][p * 2], vbh[nb][p * 2 + 1]);
                    mma_bf16(c[0], c[1], c[2], c[3], a0h, a1h, a2h, a3h,
                             vbl[nb][p * 2], vbl[nb][p * 2 + 1]);
                    mma_bf16(c[0], c[1], c[2], c[3], a0l, a1l, a2l, a3l,
                             vbh[nb][p * 2], vbh[nb][p * 2 + 1]);
                }
            }
        }
        __syncthreads();
    }

    // ---- finalize ----
    float inv[4];
#pragma unroll
    for (int slot = 0; slot < 4; ++slot) {
        float lt = l_run[slot];
        lt += __shfl_xor_sync(0xffffffffu, lt, 1);
        lt += __shfl_xor_sync(0xffffffffu, lt, 2);
        inv[slot] = 1.f / lt;
    }
    const int b = bh >> 4, h = bh & 15;
#pragma unroll
    for (int mt = 0; mt < 2; ++mt) {
#pragma unroll
        for (int half = 0; half < 2; ++half) {
            const size_t orow = (size_t)b * SEQ + q0 + w * 32 + mt * 16 + row0 + half * 8;
            const float iv = inv[mt * 2 + half];
#pragma unroll
            for (int nt = 0; nt < 8; ++nt) {
                const int col = h * DHEAD + nt * 8 + coll;
                const float v0 = oacc[mt][nt][half * 2 + 0] * iv;
                const float v1 = oacc[mt][nt][half * 2 + 1] * iv;
                __nv_bfloat16 h0, l0, h1, l1;
                split2(v0, h0, l0); split2(v1, h1, l1);
                *(uint32_t*)(s_a_hi + orow * DIM + col) = packbf(h0, h1);
                *(uint32_t*)(s_a_lo + orow * DIM + col) = packbf(l0, l1);
            }
        }
    }
}

// ---------------------------------------------------------------------------
extern "C" void kernel_launch(void* const* d_in, const int* in_sizes, int n_in,
                              void* d_out, int out_size)
{
    const float* x      = (const float*)d_in[0];
    const float* w_attn = (const float*)d_in[1];
    const float* b_attn = (const float*)d_in[2];
    const float* w_proj = (const float*)d_in[3];
    const float* b_proj = (const float*)d_in[4];
    float* out = (float*)d_out;

    __nv_bfloat16 *xa_hi, *xa_lo, *wq_hi, *wq_lo, *wp_hi, *wp_lo;
    cudaGetSymbolAddress((void**)&xa_hi, s_a_hi);
    cudaGetSymbolAddress((void**)&xa_lo, s_a_lo);
    cudaGetSymbolAddress((void**)&wq_hi, s_wq_hi);
    cudaGetSymbolAddress((void**)&wq_lo, s_wq_lo);
    cudaGetSymbolAddress((void**)&wp_hi, s_wp_hi);
    cudaGetSymbolAddress((void**)&wp_lo, s_wp_lo);

    cudaFuncSetAttribute(tc_gemm_kernel,
                         cudaFuncAttributeMaxDynamicSharedMemorySize, GSM_BYTES);
    cudaFuncSetAttribute(attn_tc_kernel,
                         cudaFuncAttributeMaxDynamicSharedMemorySize, ASM_BYTES);

    // 1) split x -> bf16 hi/lo
    split_kernel<<<(MROWS * KTOT / 4 + 255) / 256, 256>>>(x, xa_hi, xa_lo, MROWS * KTOT / 4);
    // 2) transpose+split weights
    transp_split_kernel<<<dim3(NQKV / 32, KTOT / 32), dim3(32, 8)>>>(w_attn, KTOT, NQKV, wq_hi, wq_lo);
    transp_split_kernel<<<dim3(DIM / 32, KTOT / 32), dim3(32, 8)>>>(w_proj, KTOT, DIM, wp_hi, wp_lo);
    // 3) QKV GEMM -> bf16 split q/k/vt
    tc_gemm_kernel<<<dim3(NQKV / BN, MROWS / BM), 256, GSM_BYTES>>>(
        xa_hi, xa_lo, wq_hi, wq_lo, b_attn, nullptr, 0);
    // 4) tensor-core flash attention -> writes s_a_hi/s_a_lo
    attn_tc_kernel<<<dim3(SEQ / 128, BATCH * NHEAD), 128, ASM_BYTES>>>();
    // 5) output projection
    tc_gemm_kernel<<<dim3(DIM / BN, MROWS / BM), 256, GSM_BYTES>>>(
        xa_hi, xa_lo, wp_hi, wp_lo, b_proj, out, 1);
}